// round 9
// baseline (speedup 1.0000x reference)
#include <cuda_runtime.h>
#include <cuda_bf16.h>

#define NEG_SLOPE 0.01f

// ---------------- device scratch (precomputed / transposed weights) ----------------
__device__ float g_cw[3 * 32 * 9];      // folded (wt/wp/wg @ w1) 3x3 conv weights
__device__ float g_cb[3 * 32];          // folded biases
__device__ float g_w2s[64 * 9 * 32];    // w2 scalar: [(ic*9+j)*32+oc]
__device__ float g_wod[32 * 128];       // wo dup-pairs: [c*64+oc] -> (w,w) u64
__device__ float g_dw1t[200 * 64];      // dense weights transposed: [k][oc]
__device__ float g_dw2t[64 * 32];
__device__ float g_dw3t[32 * 16];
__device__ float g_dw4t[16 * 8];

__device__ __forceinline__ float lrelu(float v) {
    return v >= 0.0f ? v : NEG_SLOPE * v;
}

// packed f32x2 helpers (sm_103a dual-FMA pipe)
__device__ __forceinline__ unsigned long long pk2(float lo, float hi) {
    unsigned long long d;
    asm("mov.b64 %0, {%1, %2};" : "=l"(d) : "f"(lo), "f"(hi));
    return d;
}
__device__ __forceinline__ void upk2(unsigned long long d, float& lo, float& hi) {
    asm("mov.b64 {%0, %1}, %2;" : "=f"(lo), "=f"(hi) : "l"(d));
}
__device__ __forceinline__ unsigned long long ffma2(unsigned long long a, unsigned long long b,
                                                    unsigned long long c) {
    unsigned long long d;
    asm("fma.rn.f32x2 %0, %1, %2, %3;" : "=l"(d) : "l"(a), "l"(b), "l"(c));
    return d;
}
__device__ __forceinline__ unsigned long long add2(unsigned long long a, unsigned long long b) {
    unsigned long long d;
    asm("add.rn.f32x2 %0, %1, %2;" : "=l"(d) : "l"(a), "l"(b));
    return d;
}

// ---------------- setup kernel ----------------
__global__ void braggnn_prep(const float* __restrict__ w1, const float* __restrict__ b1,
                             const float* __restrict__ wt, const float* __restrict__ bt,
                             const float* __restrict__ wp, const float* __restrict__ bp,
                             const float* __restrict__ wg, const float* __restrict__ bg,
                             const float* __restrict__ wo, const float* __restrict__ w2,
                             const float* __restrict__ dw1, const float* __restrict__ dw2,
                             const float* __restrict__ dw3, const float* __restrict__ dw4) {
    int tid = blockIdx.x * blockDim.x + threadIdx.x;
    int nth = gridDim.x * blockDim.x;

    for (int i = tid; i < 3 * 32 * 9; i += nth) {
        int which = i / (32 * 9);
        int c = (i / 9) % 32;
        int k = i % 9;
        const float* wX = (which == 0) ? wt : ((which == 1) ? wp : wg);
        float s = 0.0f;
        for (int oc = 0; oc < 64; oc++) s += wX[c * 64 + oc] * w1[oc * 9 + k];
        g_cw[i] = s;
    }
    for (int i = tid; i < 3 * 32; i += nth) {
        int which = i / 32;
        int c = i % 32;
        const float* wX = (which == 0) ? wt : ((which == 1) ? wp : wg);
        const float* bX = (which == 0) ? bt : ((which == 1) ? bp : bg);
        float s = bX[c];
        for (int oc = 0; oc < 64; oc++) s += wX[c * 64 + oc] * b1[oc];
        g_cb[i] = s;
    }
    // w2 scalar: [(ic*9+j)*32+oc]
    for (int i = tid; i < 64 * 9 * 32; i += nth) {
        int oc = i % 32;
        int j = (i / 32) % 9;
        int ic = i / (32 * 9);
        g_w2s[i] = w2[(oc * 64 + ic) * 9 + j];
    }
    // wo dup-pairs: pair index c*64+oc
    for (int i = tid; i < 32 * 64; i += nth) {
        int oc = i % 64, c = i / 64;
        float w = wo[oc * 32 + c];
        g_wod[2 * i] = w;
        g_wod[2 * i + 1] = w;
    }
    for (int i = tid; i < 200 * 64; i += nth) { int o = i % 64, k = i / 64; g_dw1t[i] = dw1[o * 200 + k]; }
    for (int i = tid; i < 64 * 32; i += nth)  { int o = i % 32, k = i / 32; g_dw2t[i] = dw2[o * 64 + k]; }
    for (int i = tid; i < 32 * 16; i += nth)  { int o = i % 16, k = i / 16; g_dw3t[i] = dw3[o * 32 + k]; }
    for (int i = tid; i < 16 * 8; i += nth)   { int o = i % 8,  k = i / 8;  g_dw4t[i] = dw4[o * 16 + k]; }
}

// ---------------- shared memory layout (floats), with overlays ----------------
// HS  [64][9][12] = 6912 @0     (h, live through stage E)
// AGS [32][9][12] = 3456 @6912  (attn*g, stages C/D) ... overlaid after D by:
//   H2S/RED0 [32][58] @6912  (stage E partials; finale writes conv2 out in place)
//   RED1     [32][58] @8768  (dead after stage E; overlaid by H3S/P1S/D*)
// H3S 200 @8768 | P1S 128 @8968 | D1S 64 @9096 | D2S 32 @9160 | D3S 16 @9192 | D4S 8 @9208
// XS 124 @10368 | W1S 576 @10492 | B1S 64 @11068  (dead after stage C; RED1 tail overlays)
#define HS    0
#define AGS   6912
#define H2S   6912
#define RED1  8768
#define H3S   8768
#define P1S   8968
#define D1S   9096
#define D2S   9160
#define D3S   9192
#define D4S   9208
#define XS    10368
#define W1S   10492
#define B1S   11068
#define SM_TOTAL 11132   // 44528 bytes -> 5 blocks/SM

__global__ void __launch_bounds__(128, 5)
braggnn_main(const float* __restrict__ x,
             const float* __restrict__ w1, const float* __restrict__ b1,
             const float* __restrict__ bo, const float* __restrict__ b2,
             const float* __restrict__ w3, const float* __restrict__ b3,
             const float* __restrict__ db1, const float* __restrict__ db2,
             const float* __restrict__ db3, const float* __restrict__ db4,
             const float* __restrict__ dw5, const float* __restrict__ db5,
             float* __restrict__ out) {
    __shared__ __align__(16) float sm[SM_TOTAL];
    const int s = blockIdx.x;
    const int t = threadIdx.x;

    // ---- stage 0: load x + conv1 weights ----
    for (int i = t; i < 121; i += 128) sm[XS + i] = x[s * 121 + i];
    for (int i = t; i < 576; i += 128) sm[W1S + i] = w1[i];
    if (t < 64) sm[B1S + t] = b1[t];
    __syncthreads();

    // ---- stage B: conv1 (1->64, 3x3, 11x11 -> 9x9), padded rows of 12 ----
    {
        int oc = t >> 1, half = t & 1;
        float wv[9];
        #pragma unroll
        for (int j = 0; j < 9; j++) wv[j] = sm[W1S + oc * 9 + j];
        float bias = sm[B1S + oc];
        int r0 = half ? 5 : 0;
        int r1 = half ? 9 : 5;
        for (int r = r0; r < r1; r++) {
            float xr[3][11];
            #pragma unroll
            for (int i = 0; i < 3; i++)
                #pragma unroll
                for (int c = 0; c < 11; c++) xr[i][c] = sm[XS + (r + i) * 11 + c];
            float* hrow = &sm[HS + oc * 108 + r * 12];
            #pragma unroll
            for (int col = 0; col < 9; col++) {
                float acc = bias;
                #pragma unroll
                for (int kh = 0; kh < 3; kh++)
                    #pragma unroll
                    for (int kw = 0; kw < 3; kw++)
                        acc += wv[kh * 3 + kw] * xr[kh][col + kw];
                hrow[col] = acc;
            }
            hrow[9] = 0.0f; hrow[10] = 0.0f; hrow[11] = 0.0f;
        }
    }
    __syncthreads();

    // ---- stage C: folded theta/phi/g convs + softmax over W + mul by g ----
    for (int task = t; task < 288; task += 128) {
        int c = task / 9, row = task - c * 9;
        float cwt_[9], cwp_[9], cwg_[9];
        #pragma unroll
        for (int j = 0; j < 9; j++) {
            cwt_[j] = __ldg(&g_cw[c * 9 + j]);
            cwp_[j] = __ldg(&g_cw[288 + c * 9 + j]);
            cwg_[j] = __ldg(&g_cw[576 + c * 9 + j]);
        }
        float xr[3][11];
        #pragma unroll
        for (int i = 0; i < 3; i++)
            #pragma unroll
            for (int cc = 0; cc < 11; cc++) xr[i][cc] = sm[XS + (row + i) * 11 + cc];
        float th[9], ph[9], gg[9];
        float cb0 = __ldg(&g_cb[c]), cb1 = __ldg(&g_cb[32 + c]), cb2 = __ldg(&g_cb[64 + c]);
        #pragma unroll
        for (int col = 0; col < 9; col++) { th[col] = cb0; ph[col] = cb1; gg[col] = cb2; }
        #pragma unroll
        for (int kh = 0; kh < 3; kh++) {
            #pragma unroll
            for (int kw = 0; kw < 3; kw++) {
                float wT = cwt_[kh * 3 + kw];
                float wP = cwp_[kh * 3 + kw];
                float wG = cwg_[kh * 3 + kw];
                #pragma unroll
                for (int col = 0; col < 9; col++) {
                    float xv = xr[kh][col + kw];
                    th[col] += wT * xv;
                    ph[col] += wP * xv;
                    gg[col] += wG * xv;
                }
            }
        }
        float v[9], mx = -1e30f;
        #pragma unroll
        for (int col = 0; col < 9; col++) { v[col] = th[col] * ph[col]; mx = fmaxf(mx, v[col]); }
        float ssum = 0.0f;
        #pragma unroll
        for (int col = 0; col < 9; col++) { float e = __expf(v[col] - mx); ssum += e; v[col] = e; }
        float inv = 1.0f / ssum;
        float* agrow = &sm[AGS + c * 108 + row * 12];
        #pragma unroll
        for (int col = 0; col < 9; col++) agrow[col] = v[col] * inv * gg[col];
        agrow[9] = 0.0f; agrow[10] = 0.0f; agrow[11] = 0.0f;
    }
    __syncthreads();

    // ---- stage D: o = wo @ (attn*g) + bo ; h = lrelu(o + h), packed f32x2 ----
    {
        int oc = t & 63, half = t >> 6;
        int ch0 = half ? 14 : 0;
        int ch1 = half ? 27 : 14;
        const unsigned long long* wod = (const unsigned long long*)g_wod;
        unsigned long long ww[32];
        #pragma unroll
        for (int c = 0; c < 32; c++) ww[c] = __ldg(&wod[c * 64 + oc]);
        float bov = __ldg(&bo[oc]);
        unsigned long long bb = pk2(bov, bov);
        for (int ch = ch0; ch < ch1; ch++) {
            unsigned long long a01 = bb, a23 = bb;
            #pragma unroll
            for (int c = 0; c < 32; c++) {
                ulonglong2 g2 = *(const ulonglong2*)&sm[AGS + c * 108 + ch * 4];
                a01 = ffma2(g2.x, ww[c], a01);
                a23 = ffma2(g2.y, ww[c], a23);
            }
            float4 hv = *(const float4*)&sm[HS + oc * 108 + ch * 4];
            float r0, r1, r2, r3;
            upk2(a01, r0, r1);
            upk2(a23, r2, r3);
            r0 = lrelu(r0 + hv.x);
            r1 = lrelu(r1 + hv.y);
            r2 = lrelu(r2 + hv.z);
            r3 = lrelu(r3 + hv.w);
            if (ch % 3 == 2) { r1 = 0.0f; r2 = 0.0f; r3 = 0.0f; }  // pad cols 9..11
            *(float4*)&sm[HS + oc * 108 + ch * 4] = make_float4(r0, r1, r2, r3);
        }
    }
    __syncthreads();

    // ---- stage E: conv2 (64->32, 3x3, 9x9 -> 7x7), warp=ic-group, lane=oc ----
    // Software-pipelined weights (full next-ic batch prefetched) + slim accs:
    // 3 f32x2 pairs (cols 0-5) + 1 scalar (col 6) per output row.
    {
        int wg = t >> 5, oc = t & 31;
        float b2v = __ldg(&b2[oc]);
        unsigned long long acc[7][3];
        float accs[7];
        #pragma unroll
        for (int a = 0; a < 7; a++) {
            #pragma unroll
            for (int b = 0; b < 3; b++) acc[a][b] = 0ULL;
            accs[a] = 0.0f;
        }

        int ic0 = wg * 16;
        float wn[9];
        #pragma unroll
        for (int j = 0; j < 9; j++) wn[j] = __ldg(&g_w2s[(ic0 * 9 + j) * 32 + oc]);

        #pragma unroll 1
        for (int il = 0; il < 16; il++) {
            int ic = ic0 + il;
            unsigned long long wd[9];
            #pragma unroll
            for (int j = 0; j < 9; j++) wd[j] = pk2(wn[j], wn[j]);
            if (il < 15) {
                #pragma unroll
                for (int j = 0; j < 9; j++) wn[j] = __ldg(&g_w2s[((ic + 1) * 9 + j) * 32 + oc]);
            }
            #pragma unroll
            for (int r = 0; r < 9; r++) {
                const float* rb = &sm[HS + ic * 108 + r * 12];
                ulonglong2 pA = *(const ulonglong2*)rb;        // (c0,c1),(c2,c3)
                ulonglong2 pB = *(const ulonglong2*)(rb + 4);  // (c4,c5),(c6,c7)
                unsigned long long p4 = *(const unsigned long long*)(rb + 8);  // (c8,pad)
                float f0, f1, f2, f3, f4, f5, f6, f7, f8, f9;
                upk2(pA.x, f0, f1);
                upk2(pA.y, f2, f3);
                upk2(pB.x, f4, f5);
                upk2(pB.y, f6, f7);
                upk2(p4, f8, f9);
                unsigned long long o0 = pk2(f1, f2), o1 = pk2(f3, f4), o2 = pk2(f5, f6);
                #pragma unroll
                for (int kh = 0; kh < 3; kh++) {
                    int orow = r - kh;
                    if (orow < 0 || orow > 6) continue;
                    unsigned long long w0 = wd[kh * 3 + 0];
                    unsigned long long w1v = wd[kh * 3 + 1];
                    unsigned long long w2v = wd[kh * 3 + 2];
                    float ws0, ws1, ws2, dmy;
                    upk2(w0, ws0, dmy);
                    upk2(w1v, ws1, dmy);
                    upk2(w2v, ws2, dmy);
                    acc[orow][0] = ffma2(pA.x, w0, acc[orow][0]);
                    acc[orow][1] = ffma2(pA.y, w0, acc[orow][1]);
                    acc[orow][2] = ffma2(pB.x, w0, acc[orow][2]);
                    acc[orow][0] = ffma2(o0, w1v, acc[orow][0]);
                    acc[orow][1] = ffma2(o1, w1v, acc[orow][1]);
                    acc[orow][2] = ffma2(o2, w1v, acc[orow][2]);
                    acc[orow][0] = ffma2(pA.y, w2v, acc[orow][0]);
                    acc[orow][1] = ffma2(pB.x, w2v, acc[orow][1]);
                    acc[orow][2] = ffma2(pB.y, w2v, acc[orow][2]);
                    accs[orow] = fmaf(ws0, f6, accs[orow]);
                    accs[orow] = fmaf(ws1, f7, accs[orow]);
                    accs[orow] = fmaf(ws2, f8, accs[orow]);
                }
            }
        }

        // reduction: wg1 -> H2S(RED0), wg3 -> RED1; wg0 += H2S in place;
        // wg2 += RED1 in place; then ALL warps finalize assigned rows in place.
        if (wg == 1 || wg == 3) {
            float* red = &sm[(wg == 1 ? H2S : RED1) + oc * 58];
            #pragma unroll
            for (int a = 0; a < 7; a++) {
                #pragma unroll
                for (int b = 0; b < 3; b++)
                    *(unsigned long long*)&red[a * 8 + 2 * b] = acc[a][b];
                red[a * 8 + 6] = accs[a];
            }
        }
        __syncthreads();
        if (wg == 0 || wg == 2) {
            float* red = &sm[(wg == 0 ? H2S : RED1) + oc * 58];
            #pragma unroll
            for (int a = 0; a < 7; a++) {
                #pragma unroll
                for (int b = 0; b < 3; b++) {
                    unsigned long long v = add2(acc[a][b], *(const unsigned long long*)&red[a * 8 + 2 * b]);
                    *(unsigned long long*)&red[a * 8 + 2 * b] = v;
                }
                red[a * 8 + 6] += accs[a];
            }
        }
        __syncthreads();
        {
            int a0 = wg * 2;
            int nr = (wg < 3) ? 2 : 1;
            for (int ar = 0; ar < nr; ar++) {
                int a = a0 + ar;
                #pragma unroll
                for (int b = 0; b < 3; b++) {
                    unsigned long long v = add2(
                        *(const unsigned long long*)&sm[H2S + oc * 58 + a * 8 + 2 * b],
                        *(const unsigned long long*)&sm[RED1 + oc * 58 + a * 8 + 2 * b]);
                    float v0, v1;
                    upk2(v, v0, v1);
                    sm[H2S + oc * 58 + a * 8 + 2 * b] = lrelu(v0 + b2v);
                    sm[H2S + oc * 58 + a * 8 + 2 * b + 1] = lrelu(v1 + b2v);
                }
                float v6 = sm[H2S + oc * 58 + a * 8 + 6] + sm[RED1 + oc * 58 + a * 8 + 6];
                sm[H2S + oc * 58 + a * 8 + 6] = lrelu(v6 + b2v);
            }
        }
    }
    __syncthreads();

    // ---- stage F: conv3 (32->8, 3x3, 7x7 -> 5x5) + lrelu ----
    if (t < 120) {
        int oc = t / 15, rem = t - oc * 15;
        int orow = rem / 3, cg = rem - orow * 3;
        int c0 = cg * 2;
        float acc0 = 0.0f, acc1 = 0.0f;
        #pragma unroll 1
        for (int ic = 0; ic < 32; ic++) {
            const float* wb = &w3[(oc * 32 + ic) * 9];
            const float* hb = &sm[H2S + ic * 58 + orow * 8 + c0];
            float in[3][4];
            #pragma unroll
            for (int kh = 0; kh < 3; kh++) {
                float2 a = *(const float2*)(hb + kh * 8);
                float2 b = *(const float2*)(hb + kh * 8 + 2);
                in[kh][0] = a.x; in[kh][1] = a.y; in[kh][2] = b.x; in[kh][3] = b.y;
            }
            #pragma unroll
            for (int kh = 0; kh < 3; kh++)
                #pragma unroll
                for (int kw = 0; kw < 3; kw++) {
                    float w = __ldg(&wb[kh * 3 + kw]);
                    acc0 += w * in[kh][kw];
                    acc1 += w * in[kh][kw + 1];
                }
        }
        float b3v = __ldg(&b3[oc]);
        sm[H3S + oc * 25 + orow * 5 + c0] = lrelu(acc0 + b3v);
        if (cg < 2) sm[H3S + oc * 25 + orow * 5 + c0 + 1] = lrelu(acc1 + b3v);
    }
    __syncthreads();

    // ---- stage G: dense head ----
    {
        int oc = t & 63, half = t >> 6;
        int k0 = half * 100;
        float a0 = 0.0f, a1 = 0.0f;
        #pragma unroll 4
        for (int k = 0; k < 100; k += 2) {
            a0 += g_dw1t[(k0 + k) * 64 + oc] * sm[H3S + k0 + k];
            a1 += g_dw1t[(k0 + k + 1) * 64 + oc] * sm[H3S + k0 + k + 1];
        }
        sm[P1S + t] = a0 + a1;
    }
    __syncthreads();
    if (t < 64) sm[D1S + t] = lrelu(sm[P1S + t] + sm[P1S + 64 + t] + __ldg(&db1[t]));
    __syncthreads();
    if (t < 32) {
        float acc = __ldg(&db2[t]);
        #pragma unroll 4
        for (int k = 0; k < 64; k++) acc += g_dw2t[k * 32 + t] * sm[D1S + k];
        sm[D2S + t] = lrelu(acc);
    }
    __syncthreads();
    if (t < 16) {
        float acc = __ldg(&db3[t]);
        #pragma unroll
        for (int k = 0; k < 32; k++) acc += g_dw3t[k * 16 + t] * sm[D2S + k];
        sm[D3S + t] = lrelu(acc);
    }
    __syncthreads();
    if (t < 8) {
        float acc = __ldg(&db4[t]);
        #pragma unroll
        for (int k = 0; k < 16; k++) acc += g_dw4t[k * 8 + t] * sm[D3S + k];
        sm[D4S + t] = lrelu(acc);
    }
    __syncthreads();
    if (t < 2) {
        float acc = __ldg(&db5[t]);
        #pragma unroll
        for (int k = 0; k < 8; k++) acc += __ldg(&dw5[t * 8 + k]) * sm[D4S + k];
        out[s * 2 + t] = acc;
    }
}

// ---------------- launch ----------------
extern "C" void kernel_launch(void* const* d_in, const int* in_sizes, int n_in,
                              void* d_out, int out_size) {
    const float* x   = (const float*)d_in[0];
    const float* w1  = (const float*)d_in[1];
    const float* b1  = (const float*)d_in[2];
    const float* wt  = (const float*)d_in[3];
    const float* bt  = (const float*)d_in[4];
    const float* wp  = (const float*)d_in[5];
    const float* bp  = (const float*)d_in[6];
    const float* wg  = (const float*)d_in[7];
    const float* bg  = (const float*)d_in[8];
    const float* wo  = (const float*)d_in[9];
    const float* bo  = (const float*)d_in[10];
    const float* w2  = (const float*)d_in[11];
    const float* b2  = (const float*)d_in[12];
    const float* w3  = (const float*)d_in[13];
    const float* b3  = (const float*)d_in[14];
    const float* dw1 = (const float*)d_in[15];
    const float* db1 = (const float*)d_in[16];
    const float* dw2 = (const float*)d_in[17];
    const float* db2 = (const float*)d_in[18];
    const float* dw3 = (const float*)d_in[19];
    const float* db3 = (const float*)d_in[20];
    const float* dw4 = (const float*)d_in[21];
    const float* db4 = (const float*)d_in[22];
    const float* dw5 = (const float*)d_in[23];
    const float* db5 = (const float*)d_in[24];
    float* out = (float*)d_out;

    braggnn_prep<<<40, 256>>>(w1, b1, wt, bt, wp, bp, wg, bg, wo, w2, dw1, dw2, dw3, dw4);
    braggnn_main<<<16384, 128>>>(x, w1, b1, bo, b2, w3, b3,
                                 db1, db2, db3, db4, dw5, db5, out);
}

// round 10
// speedup vs baseline: 2.9712x; 2.9712x over previous
#include <cuda_runtime.h>
#include <cuda_bf16.h>

#define NEG_SLOPE 0.01f

// ---------------- device scratch (precomputed / transposed weights) ----------------
__device__ float g_cw[3 * 32 * 9];      // folded (wt/wp/wg @ w1) 3x3 conv weights
__device__ float g_cb[3 * 32];          // folded biases
__device__ float g_w2s[64 * 9 * 32];    // w2 scalar: [(ic*9+j)*32+oc]
__device__ float g_wod[32 * 128];       // wo dup-pairs: [c*64+oc] -> (w,w) u64
__device__ float g_dw1t[200 * 64];      // dense weights transposed: [k][oc]
__device__ float g_dw2t[64 * 32];
__device__ float g_dw3t[32 * 16];
__device__ float g_dw4t[16 * 8];

__device__ __forceinline__ float lrelu(float v) {
    return v >= 0.0f ? v : NEG_SLOPE * v;
}

// packed f32x2 helpers (sm_103a dual-FMA pipe)
__device__ __forceinline__ unsigned long long pk2(float lo, float hi) {
    unsigned long long d;
    asm("mov.b64 %0, {%1, %2};" : "=l"(d) : "f"(lo), "f"(hi));
    return d;
}
__device__ __forceinline__ void upk2(unsigned long long d, float& lo, float& hi) {
    asm("mov.b64 {%0, %1}, %2;" : "=f"(lo), "=f"(hi) : "l"(d));
}
__device__ __forceinline__ unsigned long long ffma2(unsigned long long a, unsigned long long b,
                                                    unsigned long long c) {
    unsigned long long d;
    asm("fma.rn.f32x2 %0, %1, %2, %3;" : "=l"(d) : "l"(a), "l"(b), "l"(c));
    return d;
}
__device__ __forceinline__ unsigned long long add2(unsigned long long a, unsigned long long b) {
    unsigned long long d;
    asm("add.rn.f32x2 %0, %1, %2;" : "=l"(d) : "l"(a), "l"(b));
    return d;
}

// ---------------- setup kernel ----------------
__global__ void braggnn_prep(const float* __restrict__ w1, const float* __restrict__ b1,
                             const float* __restrict__ wt, const float* __restrict__ bt,
                             const float* __restrict__ wp, const float* __restrict__ bp,
                             const float* __restrict__ wg, const float* __restrict__ bg,
                             const float* __restrict__ wo, const float* __restrict__ w2,
                             const float* __restrict__ dw1, const float* __restrict__ dw2,
                             const float* __restrict__ dw3, const float* __restrict__ dw4) {
    int tid = blockIdx.x * blockDim.x + threadIdx.x;
    int nth = gridDim.x * blockDim.x;

    for (int i = tid; i < 3 * 32 * 9; i += nth) {
        int which = i / (32 * 9);
        int c = (i / 9) % 32;
        int k = i % 9;
        const float* wX = (which == 0) ? wt : ((which == 1) ? wp : wg);
        float s = 0.0f;
        for (int oc = 0; oc < 64; oc++) s += wX[c * 64 + oc] * w1[oc * 9 + k];
        g_cw[i] = s;
    }
    for (int i = tid; i < 3 * 32; i += nth) {
        int which = i / 32;
        int c = i % 32;
        const float* wX = (which == 0) ? wt : ((which == 1) ? wp : wg);
        const float* bX = (which == 0) ? bt : ((which == 1) ? bp : bg);
        float s = bX[c];
        for (int oc = 0; oc < 64; oc++) s += wX[c * 64 + oc] * b1[oc];
        g_cb[i] = s;
    }
    // w2 scalar: [(ic*9+j)*32+oc]
    for (int i = tid; i < 64 * 9 * 32; i += nth) {
        int oc = i % 32;
        int j = (i / 32) % 9;
        int ic = i / (32 * 9);
        g_w2s[i] = w2[(oc * 64 + ic) * 9 + j];
    }
    // wo dup-pairs: pair index c*64+oc
    for (int i = tid; i < 32 * 64; i += nth) {
        int oc = i % 64, c = i / 64;
        float w = wo[oc * 32 + c];
        g_wod[2 * i] = w;
        g_wod[2 * i + 1] = w;
    }
    for (int i = tid; i < 200 * 64; i += nth) { int o = i % 64, k = i / 64; g_dw1t[i] = dw1[o * 200 + k]; }
    for (int i = tid; i < 64 * 32; i += nth)  { int o = i % 32, k = i / 32; g_dw2t[i] = dw2[o * 64 + k]; }
    for (int i = tid; i < 32 * 16; i += nth)  { int o = i % 16, k = i / 16; g_dw3t[i] = dw3[o * 32 + k]; }
    for (int i = tid; i < 16 * 8; i += nth)   { int o = i % 8,  k = i / 8;  g_dw4t[i] = dw4[o * 16 + k]; }
}

// ---------------- shared memory layout (floats), with overlays ----------------
// HS  [64][9][12] = 6912 @0     (h, live through stage E)
// AGS [32][9][12] = 3456 @6912  (attn*g, stages C/D) ... overlaid after D by:
//   H2S/RED0 [32][58] @6912  (stage E partials; finale writes conv2 out in place)
//   RED1     [32][58] @8768  (dead after stage E; overlaid by H3S/P1S/D*)
// H3S 200 @8768 | P1S 128 @8968 | D1S 64 @9096 | D2S 32 @9160 | D3S 16 @9192 | D4S 8 @9208
// XS 124 @10368 | W1S 576 @10492 | B1S 64 @11068  (dead after stage C; RED1 tail overlays)
#define HS    0
#define AGS   6912
#define H2S   6912
#define RED1  8768
#define H3S   8768
#define P1S   8968
#define D1S   9096
#define D2S   9160
#define D3S   9192
#define D4S   9208
#define XS    10368
#define W1S   10492
#define B1S   11068
#define SM_TOTAL 11132   // 44528 bytes -> 5 blocks/SM

__global__ void __launch_bounds__(128, 5)
braggnn_main(const float* __restrict__ x,
             const float* __restrict__ w1, const float* __restrict__ b1,
             const float* __restrict__ bo, const float* __restrict__ b2,
             const float* __restrict__ w3, const float* __restrict__ b3,
             const float* __restrict__ db1, const float* __restrict__ db2,
             const float* __restrict__ db3, const float* __restrict__ db4,
             const float* __restrict__ dw5, const float* __restrict__ db5,
             float* __restrict__ out) {
    __shared__ __align__(16) float sm[SM_TOTAL];
    const int s = blockIdx.x;
    const int t = threadIdx.x;

    // ---- stage 0: load x + conv1 weights ----
    for (int i = t; i < 121; i += 128) sm[XS + i] = x[s * 121 + i];
    for (int i = t; i < 576; i += 128) sm[W1S + i] = w1[i];
    if (t < 64) sm[B1S + t] = b1[t];
    __syncthreads();

    // ---- stage B: conv1 (1->64, 3x3, 11x11 -> 9x9), padded rows of 12 ----
    {
        int oc = t >> 1, half = t & 1;
        float wv[9];
        #pragma unroll
        for (int j = 0; j < 9; j++) wv[j] = sm[W1S + oc * 9 + j];
        float bias = sm[B1S + oc];
        int r0 = half ? 5 : 0;
        int r1 = half ? 9 : 5;
        for (int r = r0; r < r1; r++) {
            float xr[3][11];
            #pragma unroll
            for (int i = 0; i < 3; i++)
                #pragma unroll
                for (int c = 0; c < 11; c++) xr[i][c] = sm[XS + (r + i) * 11 + c];
            float* hrow = &sm[HS + oc * 108 + r * 12];
            #pragma unroll
            for (int col = 0; col < 9; col++) {
                float acc = bias;
                #pragma unroll
                for (int kh = 0; kh < 3; kh++)
                    #pragma unroll
                    for (int kw = 0; kw < 3; kw++)
                        acc += wv[kh * 3 + kw] * xr[kh][col + kw];
                hrow[col] = acc;
            }
            hrow[9] = 0.0f; hrow[10] = 0.0f; hrow[11] = 0.0f;
        }
    }
    // NO __syncthreads() here: stage C reads only XS (ready since stage 0) and
    // writes AGS; stage B writes HS. Disjoint regions — the barrier after
    // stage C orders both HS and AGS before stage D. Early-finishing warps
    // flow straight into stage C, absorbing stage B's 4/5-row skew.

    // ---- stage C: folded theta/phi/g convs + softmax over W + mul by g ----
    for (int task = t; task < 288; task += 128) {
        int c = task / 9, row = task - c * 9;
        float cwt_[9], cwp_[9], cwg_[9];
        #pragma unroll
        for (int j = 0; j < 9; j++) {
            cwt_[j] = __ldg(&g_cw[c * 9 + j]);
            cwp_[j] = __ldg(&g_cw[288 + c * 9 + j]);
            cwg_[j] = __ldg(&g_cw[576 + c * 9 + j]);
        }
        float xr[3][11];
        #pragma unroll
        for (int i = 0; i < 3; i++)
            #pragma unroll
            for (int cc = 0; cc < 11; cc++) xr[i][cc] = sm[XS + (row + i) * 11 + cc];
        float th[9], ph[9], gg[9];
        float cb0 = __ldg(&g_cb[c]), cb1 = __ldg(&g_cb[32 + c]), cb2 = __ldg(&g_cb[64 + c]);
        #pragma unroll
        for (int col = 0; col < 9; col++) { th[col] = cb0; ph[col] = cb1; gg[col] = cb2; }
        #pragma unroll
        for (int kh = 0; kh < 3; kh++) {
            #pragma unroll
            for (int kw = 0; kw < 3; kw++) {
                float wT = cwt_[kh * 3 + kw];
                float wP = cwp_[kh * 3 + kw];
                float wG = cwg_[kh * 3 + kw];
                #pragma unroll
                for (int col = 0; col < 9; col++) {
                    float xv = xr[kh][col + kw];
                    th[col] += wT * xv;
                    ph[col] += wP * xv;
                    gg[col] += wG * xv;
                }
            }
        }
        float v[9], mx = -1e30f;
        #pragma unroll
        for (int col = 0; col < 9; col++) { v[col] = th[col] * ph[col]; mx = fmaxf(mx, v[col]); }
        float ssum = 0.0f;
        #pragma unroll
        for (int col = 0; col < 9; col++) { float e = __expf(v[col] - mx); ssum += e; v[col] = e; }
        float inv = 1.0f / ssum;
        float* agrow = &sm[AGS + c * 108 + row * 12];
        #pragma unroll
        for (int col = 0; col < 9; col++) agrow[col] = v[col] * inv * gg[col];
        agrow[9] = 0.0f; agrow[10] = 0.0f; agrow[11] = 0.0f;
    }
    __syncthreads();

    // ---- stage D: o = wo @ (attn*g) + bo ; h = lrelu(o + h), packed f32x2 ----
    {
        int oc = t & 63, half = t >> 6;
        int ch0 = half ? 14 : 0;
        int ch1 = half ? 27 : 14;
        const unsigned long long* wod = (const unsigned long long*)g_wod;
        unsigned long long ww[32];
        #pragma unroll
        for (int c = 0; c < 32; c++) ww[c] = __ldg(&wod[c * 64 + oc]);
        float bov = __ldg(&bo[oc]);
        unsigned long long bb = pk2(bov, bov);
        for (int ch = ch0; ch < ch1; ch++) {
            unsigned long long a01 = bb, a23 = bb;
            #pragma unroll
            for (int c = 0; c < 32; c++) {
                ulonglong2 g2 = *(const ulonglong2*)&sm[AGS + c * 108 + ch * 4];
                a01 = ffma2(g2.x, ww[c], a01);
                a23 = ffma2(g2.y, ww[c], a23);
            }
            float4 hv = *(const float4*)&sm[HS + oc * 108 + ch * 4];
            float r0, r1, r2, r3;
            upk2(a01, r0, r1);
            upk2(a23, r2, r3);
            r0 = lrelu(r0 + hv.x);
            r1 = lrelu(r1 + hv.y);
            r2 = lrelu(r2 + hv.z);
            r3 = lrelu(r3 + hv.w);
            if (ch % 3 == 2) { r1 = 0.0f; r2 = 0.0f; r3 = 0.0f; }  // pad cols 9..11
            *(float4*)&sm[HS + oc * 108 + ch * 4] = make_float4(r0, r1, r2, r3);
        }
    }
    __syncthreads();

    // ---- stage E: conv2 (64->32, 3x3, 9x9 -> 7x7), warp=ic-group, lane=oc ----
    // Each warp accumulates f32x2 partials for ALL 49 outputs over its 16 ics,
    // then a distributed smem tree reduction (all warps participate in finale).
    {
        int wg = t >> 5, oc = t & 31;
        float b2v = __ldg(&b2[oc]);
        unsigned long long acc[7][4];
        #pragma unroll
        for (int a = 0; a < 7; a++)
            #pragma unroll
            for (int b = 0; b < 4; b++) acc[a][b] = 0ULL;

        int ic0 = wg * 16;
        #pragma unroll 1
        for (int ic = ic0; ic < ic0 + 16; ic++) {
            unsigned long long wd[9];
            #pragma unroll
            for (int j = 0; j < 9; j++) {
                float w = __ldg(&g_w2s[(ic * 9 + j) * 32 + oc]);
                wd[j] = pk2(w, w);
            }
            #pragma unroll
            for (int r = 0; r < 9; r++) {
                const float* rb = &sm[HS + ic * 108 + r * 12];
                ulonglong2 pA = *(const ulonglong2*)rb;        // (c0,c1),(c2,c3)
                ulonglong2 pB = *(const ulonglong2*)(rb + 4);  // (c4,c5),(c6,c7)
                unsigned long long p4 = *(const unsigned long long*)(rb + 8);  // (c8,pad)
                float f0, f1, f2, f3, f4, f5, f6, f7, f8, f9;
                upk2(pA.x, f0, f1);
                upk2(pA.y, f2, f3);
                upk2(pB.x, f4, f5);
                upk2(pB.y, f6, f7);
                upk2(p4, f8, f9);
                unsigned long long o0 = pk2(f1, f2), o1 = pk2(f3, f4);
                unsigned long long o2 = pk2(f5, f6), o3 = pk2(f7, f8);
                #pragma unroll
                for (int kh = 0; kh < 3; kh++) {
                    int orow = r - kh;
                    if (orow < 0 || orow > 6) continue;
                    unsigned long long w0 = wd[kh * 3 + 0];
                    unsigned long long w1v = wd[kh * 3 + 1];
                    unsigned long long w2v = wd[kh * 3 + 2];
                    acc[orow][0] = ffma2(pA.x, w0, acc[orow][0]);
                    acc[orow][1] = ffma2(pA.y, w0, acc[orow][1]);
                    acc[orow][2] = ffma2(pB.x, w0, acc[orow][2]);
                    acc[orow][3] = ffma2(pB.y, w0, acc[orow][3]);
                    acc[orow][0] = ffma2(o0, w1v, acc[orow][0]);
                    acc[orow][1] = ffma2(o1, w1v, acc[orow][1]);
                    acc[orow][2] = ffma2(o2, w1v, acc[orow][2]);
                    acc[orow][3] = ffma2(o3, w1v, acc[orow][3]);
                    acc[orow][0] = ffma2(pA.y, w2v, acc[orow][0]);
                    acc[orow][1] = ffma2(pB.x, w2v, acc[orow][1]);
                    acc[orow][2] = ffma2(pB.y, w2v, acc[orow][2]);
                    acc[orow][3] = ffma2(p4, w2v, acc[orow][3]);
                }
            }
        }

        // reduction: wg1 -> H2S(RED0), wg3 -> RED1; wg0 += H2S in place;
        // wg2 += RED1 in place; then ALL warps finalize assigned rows in place.
        if (wg == 1 || wg == 3) {
            float* red = &sm[(wg == 1 ? H2S : RED1) + oc * 58];
            #pragma unroll
            for (int a = 0; a < 7; a++)
                #pragma unroll
                for (int b = 0; b < 4; b++)
                    *(unsigned long long*)&red[a * 8 + 2 * b] = acc[a][b];
        }
        __syncthreads();
        if (wg == 0 || wg == 2) {
            float* red = &sm[(wg == 0 ? H2S : RED1) + oc * 58];
            #pragma unroll
            for (int a = 0; a < 7; a++)
                #pragma unroll
                for (int b = 0; b < 4; b++) {
                    unsigned long long v = add2(acc[a][b], *(const unsigned long long*)&red[a * 8 + 2 * b]);
                    *(unsigned long long*)&red[a * 8 + 2 * b] = v;
                }
        }
        __syncthreads();
        {
            int a0 = wg * 2;
            int nr = (wg < 3) ? 2 : 1;
            for (int ar = 0; ar < nr; ar++) {
                int a = a0 + ar;
                #pragma unroll
                for (int b = 0; b < 4; b++) {
                    unsigned long long v = add2(
                        *(const unsigned long long*)&sm[H2S + oc * 58 + a * 8 + 2 * b],
                        *(const unsigned long long*)&sm[RED1 + oc * 58 + a * 8 + 2 * b]);
                    float v0, v1;
                    upk2(v, v0, v1);
                    sm[H2S + oc * 58 + a * 8 + 2 * b] = lrelu(v0 + b2v);
                    sm[H2S + oc * 58 + a * 8 + 2 * b + 1] = lrelu(v1 + b2v);  // col7 pad ok
                }
            }
        }
    }
    __syncthreads();

    // ---- stage F: conv3 (32->8, 3x3, 7x7 -> 5x5) + lrelu ----
    if (t < 120) {
        int oc = t / 15, rem = t - oc * 15;
        int orow = rem / 3, cg = rem - orow * 3;
        int c0 = cg * 2;
        float acc0 = 0.0f, acc1 = 0.0f;
        #pragma unroll 1
        for (int ic = 0; ic < 32; ic++) {
            const float* wb = &w3[(oc * 32 + ic) * 9];
            const float* hb = &sm[H2S + ic * 58 + orow * 8 + c0];
            float in[3][4];
            #pragma unroll
            for (int kh = 0; kh < 3; kh++) {
                float2 a = *(const float2*)(hb + kh * 8);
                float2 b = *(const float2*)(hb + kh * 8 + 2);
                in[kh][0] = a.x; in[kh][1] = a.y; in[kh][2] = b.x; in[kh][3] = b.y;
            }
            #pragma unroll
            for (int kh = 0; kh < 3; kh++)
                #pragma unroll
                for (int kw = 0; kw < 3; kw++) {
                    float w = __ldg(&wb[kh * 3 + kw]);
                    acc0 += w * in[kh][kw];
                    acc1 += w * in[kh][kw + 1];
                }
        }
        float b3v = __ldg(&b3[oc]);
        sm[H3S + oc * 25 + orow * 5 + c0] = lrelu(acc0 + b3v);
        if (cg < 2) sm[H3S + oc * 25 + orow * 5 + c0 + 1] = lrelu(acc1 + b3v);
    }
    __syncthreads();

    // ---- stage G: dense head ----
    {
        int oc = t & 63, half = t >> 6;
        int k0 = half * 100;
        float a0 = 0.0f, a1 = 0.0f;
        #pragma unroll 4
        for (int k = 0; k < 100; k += 2) {
            a0 += g_dw1t[(k0 + k) * 64 + oc] * sm[H3S + k0 + k];
            a1 += g_dw1t[(k0 + k + 1) * 64 + oc] * sm[H3S + k0 + k + 1];
        }
        sm[P1S + t] = a0 + a1;
    }
    __syncthreads();
    if (t < 64) sm[D1S + t] = lrelu(sm[P1S + t] + sm[P1S + 64 + t] + __ldg(&db1[t]));
    __syncthreads();
    if (t < 32) {
        float acc = __ldg(&db2[t]);
        #pragma unroll 4
        for (int k = 0; k < 64; k++) acc += g_dw2t[k * 32 + t] * sm[D1S + k];
        sm[D2S + t] = lrelu(acc);
    }
    __syncthreads();
    if (t < 16) {
        float acc = __ldg(&db3[t]);
        #pragma unroll
        for (int k = 0; k < 32; k++) acc += g_dw3t[k * 16 + t] * sm[D2S + k];
        sm[D3S + t] = lrelu(acc);
    }
    __syncthreads();
    if (t < 8) {
        float acc = __ldg(&db4[t]);
        #pragma unroll
        for (int k = 0; k < 16; k++) acc += g_dw4t[k * 8 + t] * sm[D3S + k];
        sm[D4S + t] = lrelu(acc);
    }
    __syncthreads();
    if (t < 2) {
        float acc = __ldg(&db5[t]);
        #pragma unroll
        for (int k = 0; k < 8; k++) acc += __ldg(&dw5[t * 8 + k]) * sm[D4S + k];
        out[s * 2 + t] = acc;
    }
}

// ---------------- launch ----------------
extern "C" void kernel_launch(void* const* d_in, const int* in_sizes, int n_in,
                              void* d_out, int out_size) {
    const float* x   = (const float*)d_in[0];
    const float* w1  = (const float*)d_in[1];
    const float* b1  = (const float*)d_in[2];
    const float* wt  = (const float*)d_in[3];
    const float* bt  = (const float*)d_in[4];
    const float* wp  = (const float*)d_in[5];
    const float* bp  = (const float*)d_in[6];
    const float* wg  = (const float*)d_in[7];
    const float* bg  = (const float*)d_in[8];
    const float* wo  = (const float*)d_in[9];
    const float* bo  = (const float*)d_in[10];
    const float* w2  = (const float*)d_in[11];
    const float* b2  = (const float*)d_in[12];
    const float* w3  = (const float*)d_in[13];
    const float* b3  = (const float*)d_in[14];
    const float* dw1 = (const float*)d_in[15];
    const float* db1 = (const float*)d_in[16];
    const float* dw2 = (const float*)d_in[17];
    const float* db2 = (const float*)d_in[18];
    const float* dw3 = (const float*)d_in[19];
    const float* db3 = (const float*)d_in[20];
    const float* dw4 = (const float*)d_in[21];
    const float* db4 = (const float*)d_in[22];
    const float* dw5 = (const float*)d_in[23];
    const float* db5 = (const float*)d_in[24];
    float* out = (float*)d_out;

    braggnn_prep<<<40, 256>>>(w1, b1, wt, bt, wp, bp, wg, bg, wo, w2, dw1, dw2, dw3, dw4);
    braggnn_main<<<16384, 128>>>(x, w1, b1, bo, b2, w3, b3,
                                 db1, db2, db3, db4, dw5, db5, out);
}